// round 1
// baseline (speedup 1.0000x reference)
#include <cuda_runtime.h>

#define NUM_NODES 150000
#define EMB_DIM   64
#define N_EDGES   4000000
#define N_LAYERS  3

// ---- scratch (static device globals: allowed; no allocation) ----
__device__ float g_bufA[NUM_NODES * EMB_DIM];
__device__ float g_bufB[NUM_NODES * EMB_DIM];
__device__ float g_dis[NUM_NODES];
__device__ int   g_deg[NUM_NODES];

// ---------------------------------------------------------------
__global__ void k_zero_deg() {
    int i = blockIdx.x * blockDim.x + threadIdx.x;
    if (i < NUM_NODES) g_deg[i] = 0;
}

__global__ void k_count_deg(const int* __restrict__ col) {
    int i = blockIdx.x * blockDim.x + threadIdx.x;
    if (i < N_EDGES) atomicAdd(&g_deg[col[i]], 1);
}

__global__ void k_dis() {
    int i = blockIdx.x * blockDim.x + threadIdx.x;
    if (i < NUM_NODES) {
        int d = g_deg[i];
        g_dis[i] = (d > 0) ? rsqrtf((float)d) : 0.0f;
    }
}

// init: bufA = emb_weight, out(acc) = emb_weight   (float4 wide)
__global__ void k_init(const float4* __restrict__ w, float4* __restrict__ out) {
    int i = blockIdx.x * blockDim.x + threadIdx.x;
    if (i < NUM_NODES * EMB_DIM / 4) {
        float4 v = w[i];
        ((float4*)g_bufA)[i] = v;
        out[i] = v;
    }
}

// zero destination buffer for next layer
__global__ void k_zero_buf(int parity) {
    float4* dst = parity ? (float4*)g_bufA : (float4*)g_bufB;
    int i = blockIdx.x * blockDim.x + threadIdx.x;
    if (i < NUM_NODES * EMB_DIM / 4) dst[i] = make_float4(0.f, 0.f, 0.f, 0.f);
}

// scatter: dst[col] += norm * src[row] ; 16 threads per edge, one float4 each
__global__ void k_scatter(const int* __restrict__ row,
                          const int* __restrict__ col,
                          int parity) {
    const float4* src = parity ? (const float4*)g_bufB : (const float4*)g_bufA;
    float*        dst = parity ? g_bufA : g_bufB;

    long long t = (long long)blockIdx.x * blockDim.x + threadIdx.x;
    int edge  = (int)(t >> 4);
    int chunk = (int)(t & 15);
    if (edge >= N_EDGES) return;

    int r = __ldg(&row[edge]);
    int c = __ldg(&col[edge]);
    float norm = __ldg(&g_dis[r]) * __ldg(&g_dis[c]);

    float4 v = __ldg(&src[(long long)r * 16 + chunk]);
    v.x *= norm; v.y *= norm; v.z *= norm; v.w *= norm;

    float* p = dst + ((long long)c * EMB_DIM + chunk * 4);
    asm volatile("red.global.add.v4.f32 [%0], {%1, %2, %3, %4};"
                 :: "l"(p), "f"(v.x), "f"(v.y), "f"(v.z), "f"(v.w)
                 : "memory");
}

// acc += layer result (layer result buffer indicated by parity: dst of scatter)
__global__ void k_accum(float4* __restrict__ out, int parity) {
    const float4* src = parity ? (const float4*)g_bufA : (const float4*)g_bufB;
    int i = blockIdx.x * blockDim.x + threadIdx.x;
    if (i < NUM_NODES * EMB_DIM / 4) {
        float4 a = out[i];
        float4 b = src[i];
        a.x += b.x; a.y += b.y; a.z += b.z; a.w += b.w;
        out[i] = a;
    }
}

__global__ void k_scale(float4* __restrict__ out) {
    int i = blockIdx.x * blockDim.x + threadIdx.x;
    const float s = 1.0f / (N_LAYERS + 1);
    if (i < NUM_NODES * EMB_DIM / 4) {
        float4 a = out[i];
        a.x *= s; a.y *= s; a.z *= s; a.w *= s;
        out[i] = a;
    }
}

extern "C" void kernel_launch(void* const* d_in, const int* in_sizes, int n_in,
                              void* d_out, int out_size) {
    const int*   edge = (const int*)d_in[0];     // [2, N_EDGES] int32
    const int*   row  = edge;
    const int*   col  = edge + N_EDGES;
    const float* w    = (const float*)d_in[1];   // [NUM_NODES, EMB_DIM] f32
    float*       out  = (float*)d_out;

    const int B = 256;
    const int nodes_blk  = (NUM_NODES + B - 1) / B;
    const int vec_elems  = NUM_NODES * EMB_DIM / 4;       // 2.4M float4
    const int vec_blk    = (vec_elems + B - 1) / B;
    const int edges_blk  = (N_EDGES + B - 1) / B;
    const long long scat_threads = (long long)N_EDGES * 16;
    const int scat_blk   = (int)((scat_threads + B - 1) / B);

    k_zero_deg<<<nodes_blk, B>>>();
    k_count_deg<<<edges_blk, B>>>(col);
    k_dis<<<nodes_blk, B>>>();
    k_init<<<vec_blk, B>>>((const float4*)w, (float4*)out);

    // layer l: src = parity buffer, dst = !parity ; parity starts at 0 (src=A)
    for (int l = 0; l < N_LAYERS; ++l) {
        int parity = l & 1;            // 0: A->B, 1: B->A
        k_zero_buf<<<vec_blk, B>>>(parity);
        k_scatter<<<scat_blk, B>>>(row, col, parity);
        k_accum<<<vec_blk, B>>>((float4*)out, parity);
    }
    k_scale<<<vec_blk, B>>>((float4*)out);
}

// round 3
// speedup vs baseline: 2.4668x; 2.4668x over previous
#include <cuda_runtime.h>

#define NUM_NODES 150000
#define EMB_DIM   64
#define N_EDGES   4000000
#define N_LAYERS  3
#define SCAN_B    1024
#define SCAN_GRID ((NUM_NODES + SCAN_B - 1) / SCAN_B)   // 147

// ---- scratch (static device globals: allowed; no allocation) ----
// NOTE: these symbols are referenced ONLY from device code. Taking their
// address in host code yields the host shadow (silently "works" on GB300
// via ATS and reads garbage) — that was the round-2 bug.
__device__ float g_bufA[NUM_NODES * EMB_DIM];    // layer-1 output
__device__ float g_bufB[NUM_NODES * EMB_DIM];    // layer-2 output
__device__ int2  g_csr[N_EDGES];                 // {src_row, norm_bits} grouped by col
__device__ int   g_offs[NUM_NODES + 1];          // CSR offsets
__device__ int   g_cur[NUM_NODES];               // fill cursors
__device__ int   g_deg[NUM_NODES];
__device__ float g_dis[NUM_NODES];
__device__ int   g_part[SCAN_GRID];

// ---------------------------------------------------------------
__global__ void k_zero() {
    int i = blockIdx.x * blockDim.x + threadIdx.x;
    if (i < NUM_NODES) { g_deg[i] = 0; g_cur[i] = 0; }
}

__global__ void k_count_deg(const int* __restrict__ col) {
    int i = blockIdx.x * blockDim.x + threadIdx.x;
    if (i < N_EDGES) atomicAdd(&g_deg[col[i]], 1);
}

__global__ void k_dis() {
    int i = blockIdx.x * blockDim.x + threadIdx.x;
    if (i < NUM_NODES) {
        int d = g_deg[i];
        g_dis[i] = (d > 0) ? rsqrtf((float)d) : 0.0f;
    }
}

// ---- 3-step exclusive scan of g_deg into g_offs ----
__global__ void k_scan_block() {
    __shared__ int s[SCAN_B];
    int gid = blockIdx.x * SCAN_B + threadIdx.x;
    int v = (gid < NUM_NODES) ? g_deg[gid] : 0;
    s[threadIdx.x] = v;
    __syncthreads();
    for (int off = 1; off < SCAN_B; off <<= 1) {
        int t = (threadIdx.x >= off) ? s[threadIdx.x - off] : 0;
        __syncthreads();
        s[threadIdx.x] += t;
        __syncthreads();
    }
    if (gid < NUM_NODES) g_offs[gid] = s[threadIdx.x] - v;   // exclusive
    if (threadIdx.x == SCAN_B - 1) g_part[blockIdx.x] = s[SCAN_B - 1];
}

__global__ void k_scan_part() {
    if (threadIdx.x == 0) {
        int run = 0;
        for (int i = 0; i < SCAN_GRID; ++i) {
            int v = g_part[i];
            g_part[i] = run;
            run += v;
        }
    }
}

__global__ void k_scan_add() {
    int gid = blockIdx.x * SCAN_B + threadIdx.x;
    if (gid < NUM_NODES) g_offs[gid] += g_part[blockIdx.x];
    if (gid == 0) g_offs[NUM_NODES] = N_EDGES;
}

// ---- fill CSR: group edges by destination col, precompute norm ----
__global__ void k_fill(const int* __restrict__ row, const int* __restrict__ col) {
    int e = blockIdx.x * blockDim.x + threadIdx.x;
    if (e >= N_EDGES) return;
    int r = row[e];
    int c = col[e];
    int pos = g_offs[c] + atomicAdd(&g_cur[c], 1);
    float nrm = g_dis[r] * g_dis[c];
    g_csr[pos] = make_int2(r, __float_as_int(nrm));
}

// ---- unified per-layer gather: 16 lanes per node, one float4 chunk each.
// Buffer selection happens HERE (device code) based on `layer`:
//   layer 0: src = w,      dst = g_bufA
//   layer 1: src = g_bufA, dst = g_bufB
//   layer 2: src = g_bufB, fused epilogue -> out = 0.25*(w + L1 + L2 + L3)
__global__ void k_gather(int layer,
                         const float4* __restrict__ w,
                         float4* __restrict__ out) {
    int t = blockIdx.x * blockDim.x + threadIdx.x;
    int node = t >> 4, lane = t & 15;
    if (node >= NUM_NODES) return;

    const float4* src;
    if (layer == 0)      src = w;
    else if (layer == 1) src = (const float4*)g_bufA;
    else                 src = (const float4*)g_bufB;

    int s = g_offs[node], e = g_offs[node + 1];
    float4 acc = make_float4(0.f, 0.f, 0.f, 0.f);
    #pragma unroll 2
    for (int j = s; j < e; ++j) {
        int2  pr  = g_csr[j];
        float nrm = __int_as_float(pr.y);
        float4 v  = __ldg(&src[pr.x * 16 + lane]);
        acc.x += nrm * v.x; acc.y += nrm * v.y;
        acc.z += nrm * v.z; acc.w += nrm * v.w;
    }

    int i = node * 16 + lane;
    if (layer == 0) {
        ((float4*)g_bufA)[i] = acc;
    } else if (layer == 1) {
        ((float4*)g_bufB)[i] = acc;
    } else {
        float4 a = w[i];
        float4 b = ((const float4*)g_bufA)[i];
        float4 c = ((const float4*)g_bufB)[i];
        const float q = 0.25f;
        out[i] = make_float4(q * (a.x + b.x + c.x + acc.x),
                             q * (a.y + b.y + c.y + acc.y),
                             q * (a.z + b.z + c.z + acc.z),
                             q * (a.w + b.w + c.w + acc.w));
    }
}

extern "C" void kernel_launch(void* const* d_in, const int* in_sizes, int n_in,
                              void* d_out, int out_size) {
    const int*   edge = (const int*)d_in[0];     // [2, N_EDGES] int32
    const int*   row  = edge;
    const int*   col  = edge + N_EDGES;
    const float* w    = (const float*)d_in[1];   // [NUM_NODES, EMB_DIM] f32
    float*       out  = (float*)d_out;

    const int B = 256;
    const int nodes_blk = (NUM_NODES + B - 1) / B;
    const int edges_blk = (N_EDGES + B - 1) / B;
    const long long gth = (long long)NUM_NODES * 16;
    const int gather_blk = (int)((gth + B - 1) / B);

    // ---- build CSR ----
    k_zero<<<nodes_blk, B>>>();
    k_count_deg<<<edges_blk, B>>>(col);
    k_dis<<<nodes_blk, B>>>();
    k_scan_block<<<SCAN_GRID, SCAN_B>>>();
    k_scan_part<<<1, 32>>>();
    k_scan_add<<<SCAN_GRID, SCAN_B>>>();
    k_fill<<<edges_blk, B>>>(row, col);

    // ---- 3 propagation layers, atomic-free gathers ----
    k_gather<<<gather_blk, B>>>(0, (const float4*)w, (float4*)out);
    k_gather<<<gather_blk, B>>>(1, (const float4*)w, (float4*)out);
    k_gather<<<gather_blk, B>>>(2, (const float4*)w, (float4*)out);
}

// round 5
// speedup vs baseline: 2.7477x; 1.1139x over previous
#include <cuda_runtime.h>
#include <cuda_fp16.h>

#define NUM_NODES 150000
#define EMB_DIM   64
#define N_EDGES   4000000
#define SCAN_B    1024
#define SCAN_GRID ((NUM_NODES + SCAN_B - 1) / SCAN_B)   // 147

// ---- bit-reinterpret helpers (the proper intrinsics don't exist) ----
__device__ __forceinline__ unsigned int h2_to_u32(__half2 h) {
    return *reinterpret_cast<unsigned int*>(&h);
}
__device__ __forceinline__ __half2 u32_to_h2(unsigned int u) {
    return *reinterpret_cast<__half2*>(&u);
}

// ---- scratch (static device globals; addresses taken ONLY in device code) ----
__device__ __half g_w16 [NUM_NODES * EMB_DIM];   // fp16 copy of w (layer-0 src)
__device__ __half g_l16A[NUM_NODES * EMB_DIM];   // fp16 layer-1 output
__device__ __half g_l16B[NUM_NODES * EMB_DIM];   // fp16 layer-2 output
__device__ int2   g_csr[N_EDGES];                // {src_row, norm_bits} grouped by col
__device__ int    g_offs[NUM_NODES + 1];
__device__ int    g_cur[NUM_NODES];
__device__ int    g_deg[NUM_NODES];
__device__ float  g_dis[NUM_NODES];
__device__ int    g_part[SCAN_GRID];

// ---------------------------------------------------------------
__global__ void k_zero() {
    int i = blockIdx.x * blockDim.x + threadIdx.x;
    if (i < NUM_NODES) { g_deg[i] = 0; g_cur[i] = 0; }
}

__global__ void k_count_deg(const int* __restrict__ col) {
    int i = blockIdx.x * blockDim.x + threadIdx.x;
    if (i < N_EDGES) atomicAdd(&g_deg[col[i]], 1);
}

__global__ void k_dis() {
    int i = blockIdx.x * blockDim.x + threadIdx.x;
    if (i < NUM_NODES) {
        int d = g_deg[i];
        g_dis[i] = (d > 0) ? rsqrtf((float)d) : 0.0f;
    }
}

// ---- exclusive scan of g_deg into g_offs ----
__global__ void k_scan_block() {
    __shared__ int s[SCAN_B];
    int gid = blockIdx.x * SCAN_B + threadIdx.x;
    int v = (gid < NUM_NODES) ? g_deg[gid] : 0;
    s[threadIdx.x] = v;
    __syncthreads();
    for (int off = 1; off < SCAN_B; off <<= 1) {
        int t = (threadIdx.x >= off) ? s[threadIdx.x - off] : 0;
        __syncthreads();
        s[threadIdx.x] += t;
        __syncthreads();
    }
    if (gid < NUM_NODES) g_offs[gid] = s[threadIdx.x] - v;
    if (threadIdx.x == SCAN_B - 1) g_part[blockIdx.x] = s[SCAN_B - 1];
}

__global__ void k_scan_part() {
    if (threadIdx.x == 0) {
        int run = 0;
        for (int i = 0; i < SCAN_GRID; ++i) { int v = g_part[i]; g_part[i] = run; run += v; }
    }
}

__global__ void k_scan_add() {
    int gid = blockIdx.x * SCAN_B + threadIdx.x;
    if (gid < NUM_NODES) g_offs[gid] += g_part[blockIdx.x];
    if (gid == 0) g_offs[NUM_NODES] = N_EDGES;
}

// ---- fill CSR grouped by destination col, norm precomputed ----
__global__ void k_fill(const int* __restrict__ row, const int* __restrict__ col) {
    int e = blockIdx.x * blockDim.x + threadIdx.x;
    if (e >= N_EDGES) return;
    int r = row[e];
    int c = col[e];
    int pos = g_offs[c] + atomicAdd(&g_cur[c], 1);
    g_csr[pos] = make_int2(r, __float_as_int(g_dis[r] * g_dis[c]));
}

// ---- convert w -> fp16 (layer-0 gather source) ----
__global__ void k_init16(const float4* __restrict__ w) {
    int i = blockIdx.x * blockDim.x + threadIdx.x;
    if (i < NUM_NODES * EMB_DIM / 4) {
        float4 v = w[i];
        uint2 h;
        h.x = h2_to_u32(__floats2half2_rn(v.x, v.y));
        h.y = h2_to_u32(__floats2half2_rn(v.z, v.w));
        ((uint2*)g_w16)[i] = h;
    }
}

// ---- per-layer gather: 16 lanes per node, 4 halves (8B) per lane.
// Accumulation in fp32; exact fp32 layer result folded into `out` in-register;
// quantized fp16 copy written only as the NEXT layer's gather source.
//   layer 0: src=g_w16,  dst16=g_l16A, out  = w + acc
//   layer 1: src=g_l16A, dst16=g_l16B, out += acc
//   layer 2: src=g_l16B,              out  = 0.25*(out + acc)
__global__ void k_gather(int layer,
                         const float4* __restrict__ w,
                         float4* __restrict__ out) {
    int t = blockIdx.x * blockDim.x + threadIdx.x;
    int node = t >> 4, lane = t & 15;
    if (node >= NUM_NODES) return;

    const uint2* src;
    if (layer == 0)      src = (const uint2*)g_w16;
    else if (layer == 1) src = (const uint2*)g_l16A;
    else                 src = (const uint2*)g_l16B;

    int s = g_offs[node], e = g_offs[node + 1];
    float4 acc = make_float4(0.f, 0.f, 0.f, 0.f);
    #pragma unroll 4
    for (int j = s; j < e; ++j) {
        int2  pr  = g_csr[j];
        float nrm = __int_as_float(pr.y);
        uint2 hv  = __ldg(&src[pr.x * 16 + lane]);
        float2 f0 = __half22float2(u32_to_h2(hv.x));
        float2 f1 = __half22float2(u32_to_h2(hv.y));
        acc.x += nrm * f0.x; acc.y += nrm * f0.y;
        acc.z += nrm * f1.x; acc.w += nrm * f1.y;
    }

    int i = node * 16 + lane;
    if (layer == 0) {
        uint2 h;
        h.x = h2_to_u32(__floats2half2_rn(acc.x, acc.y));
        h.y = h2_to_u32(__floats2half2_rn(acc.z, acc.w));
        ((uint2*)g_l16A)[i] = h;
        float4 a = w[i];
        out[i] = make_float4(a.x + acc.x, a.y + acc.y, a.z + acc.z, a.w + acc.w);
    } else if (layer == 1) {
        uint2 h;
        h.x = h2_to_u32(__floats2half2_rn(acc.x, acc.y));
        h.y = h2_to_u32(__floats2half2_rn(acc.z, acc.w));
        ((uint2*)g_l16B)[i] = h;
        float4 a = out[i];
        out[i] = make_float4(a.x + acc.x, a.y + acc.y, a.z + acc.z, a.w + acc.w);
    } else {
        float4 a = out[i];
        const float q = 0.25f;
        out[i] = make_float4(q * (a.x + acc.x), q * (a.y + acc.y),
                             q * (a.z + acc.z), q * (a.w + acc.w));
    }
}

extern "C" void kernel_launch(void* const* d_in, const int* in_sizes, int n_in,
                              void* d_out, int out_size) {
    const int*   edge = (const int*)d_in[0];     // [2, N_EDGES] int32
    const int*   row  = edge;
    const int*   col  = edge + N_EDGES;
    const float* w    = (const float*)d_in[1];   // [NUM_NODES, EMB_DIM] f32
    float*       out  = (float*)d_out;

    const int B = 256;
    const int nodes_blk = (NUM_NODES + B - 1) / B;
    const int edges_blk = (N_EDGES + B - 1) / B;
    const int vec_blk   = (NUM_NODES * EMB_DIM / 4 + B - 1) / B;
    const long long gth = (long long)NUM_NODES * 16;
    const int gather_blk = (int)((gth + B - 1) / B);

    // ---- build CSR + fp16 source ----
    k_zero<<<nodes_blk, B>>>();
    k_count_deg<<<edges_blk, B>>>(col);
    k_dis<<<nodes_blk, B>>>();
    k_scan_block<<<SCAN_GRID, SCAN_B>>>();
    k_scan_part<<<1, 32>>>();
    k_scan_add<<<SCAN_GRID, SCAN_B>>>();
    k_fill<<<edges_blk, B>>>(row, col);
    k_init16<<<vec_blk, B>>>((const float4*)w);

    // ---- 3 propagation layers, atomic-free fp16-source gathers ----
    k_gather<<<gather_blk, B>>>(0, (const float4*)w, (float4*)out);
    k_gather<<<gather_blk, B>>>(1, (const float4*)w, (float4*)out);
    k_gather<<<gather_blk, B>>>(2, (const float4*)w, (float4*)out);
}

// round 6
// speedup vs baseline: 2.8125x; 1.0236x over previous
#include <cuda_runtime.h>
#include <cuda_fp16.h>

#define NUM_NODES 150000
#define EMB_DIM   64
#define N_EDGES   4000000
#define SCAN_B    1024
#define SCAN_GRID ((NUM_NODES + SCAN_B - 1) / SCAN_B)   // 147

__device__ __forceinline__ unsigned int h2_to_u32(__half2 h) {
    return *reinterpret_cast<unsigned int*>(&h);
}
__device__ __forceinline__ __half2 u32_to_h2(unsigned int u) {
    return *reinterpret_cast<__half2*>(&u);
}

// ---- scratch (static device globals; addresses taken ONLY in device code) ----
__device__ __half g_w16 [NUM_NODES * EMB_DIM];   // fp16 copy of w (layer-0 src)
__device__ __half g_l16A[NUM_NODES * EMB_DIM];   // fp16 layer-1 output
__device__ __half g_l16B[NUM_NODES * EMB_DIM];   // fp16 layer-2 output
__device__ int2   g_csr[N_EDGES];                // {src_row, norm_bits} grouped by col
__device__ int    g_offs[NUM_NODES + 1];
__device__ int    g_cur[NUM_NODES];
__device__ int    g_deg[NUM_NODES];
__device__ float  g_dis[NUM_NODES];
__device__ int    g_part[SCAN_GRID];

// ---------------------------------------------------------------
__global__ void k_zero() {
    int i = blockIdx.x * blockDim.x + threadIdx.x;
    if (i < NUM_NODES) { g_deg[i] = 0; g_cur[i] = 0; }
}

__global__ void k_count_deg(const int* __restrict__ col) {
    int i = blockIdx.x * blockDim.x + threadIdx.x;
    if (i < N_EDGES) atomicAdd(&g_deg[col[i]], 1);
}

// ---- scan + dis fused: exclusive scan of g_deg into g_offs, plus g_dis ----
__global__ void k_scan_block() {
    __shared__ int s[SCAN_B];
    int gid = blockIdx.x * SCAN_B + threadIdx.x;
    int v = (gid < NUM_NODES) ? g_deg[gid] : 0;
    s[threadIdx.x] = v;
    __syncthreads();
    for (int off = 1; off < SCAN_B; off <<= 1) {
        int t = (threadIdx.x >= off) ? s[threadIdx.x - off] : 0;
        __syncthreads();
        s[threadIdx.x] += t;
        __syncthreads();
    }
    if (gid < NUM_NODES) {
        g_offs[gid] = s[threadIdx.x] - v;
        g_dis[gid] = (v > 0) ? rsqrtf((float)v) : 0.0f;
    }
    if (threadIdx.x == SCAN_B - 1) g_part[blockIdx.x] = s[SCAN_B - 1];
}

__global__ void k_scan_part() {
    if (threadIdx.x == 0) {
        int run = 0;
        for (int i = 0; i < SCAN_GRID; ++i) { int v = g_part[i]; g_part[i] = run; run += v; }
    }
}

__global__ void k_scan_add() {
    int gid = blockIdx.x * SCAN_B + threadIdx.x;
    if (gid < NUM_NODES) g_offs[gid] += g_part[blockIdx.x];
    if (gid == 0) g_offs[NUM_NODES] = N_EDGES;
}

// ---- fill CSR grouped by destination col, norm precomputed ----
__global__ void k_fill(const int* __restrict__ row, const int* __restrict__ col) {
    int e = blockIdx.x * blockDim.x + threadIdx.x;
    if (e >= N_EDGES) return;
    int r = row[e];
    int c = col[e];
    int pos = g_offs[c] + atomicAdd(&g_cur[c], 1);
    g_csr[pos] = make_int2(r, __float_as_int(g_dis[r] * g_dis[c]));
}

// ---- convert w -> fp16 (layer-0 gather source) ----
__global__ void k_init16(const float4* __restrict__ w) {
    int i = blockIdx.x * blockDim.x + threadIdx.x;
    if (i < NUM_NODES * EMB_DIM / 4) {
        float4 v = w[i];
        uint2 h;
        h.x = h2_to_u32(__floats2half2_rn(v.x, v.y));
        h.y = h2_to_u32(__floats2half2_rn(v.z, v.w));
        ((uint2*)g_w16)[i] = h;
    }
}

// ---- accumulate one fp16 row chunk (8 halves) into 8 fp32 accumulators ----
__device__ __forceinline__ void acc8(float* a, uint4 hv, float nrm) {
    float2 f0 = __half22float2(u32_to_h2(hv.x));
    float2 f1 = __half22float2(u32_to_h2(hv.y));
    float2 f2 = __half22float2(u32_to_h2(hv.z));
    float2 f3 = __half22float2(u32_to_h2(hv.w));
    a[0] += nrm * f0.x; a[1] += nrm * f0.y;
    a[2] += nrm * f1.x; a[3] += nrm * f1.y;
    a[4] += nrm * f2.x; a[5] += nrm * f2.y;
    a[6] += nrm * f3.x; a[7] += nrm * f3.y;
}

// ---- per-layer gather: 8 lanes per node, 8 halves (16B) per lane,
// 4-edge software pipeline for MLP. fp32 accumulation; exact fp32 layer
// result folded into `out`; fp16 copy is the next layer's gather source.
//   layer 0: src=g_w16,  dst16=g_l16A, out  = w + acc
//   layer 1: src=g_l16A, dst16=g_l16B, out += acc
//   layer 2: src=g_l16B,              out  = 0.25*(out + acc)
__global__ void k_gather(int layer,
                         const float4* __restrict__ w,
                         float4* __restrict__ out) {
    int t = blockIdx.x * blockDim.x + threadIdx.x;
    int node = t >> 3, lane = t & 7;
    if (node >= NUM_NODES) return;

    const uint4* src;
    if (layer == 0)      src = (const uint4*)g_w16;
    else if (layer == 1) src = (const uint4*)g_l16A;
    else                 src = (const uint4*)g_l16B;

    int s = g_offs[node], e = g_offs[node + 1];
    float acc[8] = {0.f, 0.f, 0.f, 0.f, 0.f, 0.f, 0.f, 0.f};

    int j = s;
    for (; j + 4 <= e; j += 4) {
        // batch of 4 independent edge-metadata loads
        int2 e0 = __ldg(&g_csr[j + 0]);
        int2 e1 = __ldg(&g_csr[j + 1]);
        int2 e2 = __ldg(&g_csr[j + 2]);
        int2 e3 = __ldg(&g_csr[j + 3]);
        // batch of 4 independent 16B gathers
        uint4 v0 = __ldg(&src[e0.x * 8 + lane]);
        uint4 v1 = __ldg(&src[e1.x * 8 + lane]);
        uint4 v2 = __ldg(&src[e2.x * 8 + lane]);
        uint4 v3 = __ldg(&src[e3.x * 8 + lane]);
        acc8(acc, v0, __int_as_float(e0.y));
        acc8(acc, v1, __int_as_float(e1.y));
        acc8(acc, v2, __int_as_float(e2.y));
        acc8(acc, v3, __int_as_float(e3.y));
    }
    for (; j < e; ++j) {
        int2 pr = __ldg(&g_csr[j]);
        uint4 v = __ldg(&src[pr.x * 8 + lane]);
        acc8(acc, v, __int_as_float(pr.y));
    }

    // fp16 store for next layer (layers 0,1)
    int i16 = node * 8 + lane;            // uint4 index into fp16 buffers
    if (layer != 2) {
        uint4 h;
        h.x = h2_to_u32(__floats2half2_rn(acc[0], acc[1]));
        h.y = h2_to_u32(__floats2half2_rn(acc[2], acc[3]));
        h.z = h2_to_u32(__floats2half2_rn(acc[4], acc[5]));
        h.w = h2_to_u32(__floats2half2_rn(acc[6], acc[7]));
        if (layer == 0) ((uint4*)g_l16A)[i16] = h;
        else            ((uint4*)g_l16B)[i16] = h;
    }

    // fp32 running sum in out: each lane owns two float4 slots
    int i = node * 16 + lane * 2;
    if (layer == 0) {
        float4 a0 = w[i], a1 = w[i + 1];
        out[i]     = make_float4(a0.x + acc[0], a0.y + acc[1], a0.z + acc[2], a0.w + acc[3]);
        out[i + 1] = make_float4(a1.x + acc[4], a1.y + acc[5], a1.z + acc[6], a1.w + acc[7]);
    } else if (layer == 1) {
        float4 a0 = out[i], a1 = out[i + 1];
        out[i]     = make_float4(a0.x + acc[0], a0.y + acc[1], a0.z + acc[2], a0.w + acc[3]);
        out[i + 1] = make_float4(a1.x + acc[4], a1.y + acc[5], a1.z + acc[6], a1.w + acc[7]);
    } else {
        const float q = 0.25f;
        float4 a0 = out[i], a1 = out[i + 1];
        out[i]     = make_float4(q * (a0.x + acc[0]), q * (a0.y + acc[1]),
                                 q * (a0.z + acc[2]), q * (a0.w + acc[3]));
        out[i + 1] = make_float4(q * (a1.x + acc[4]), q * (a1.y + acc[5]),
                                 q * (a1.z + acc[6]), q * (a1.w + acc[7]));
    }
}

extern "C" void kernel_launch(void* const* d_in, const int* in_sizes, int n_in,
                              void* d_out, int out_size) {
    const int*   edge = (const int*)d_in[0];     // [2, N_EDGES] int32
    const int*   row  = edge;
    const int*   col  = edge + N_EDGES;
    const float* w    = (const float*)d_in[1];   // [NUM_NODES, EMB_DIM] f32
    float*       out  = (float*)d_out;

    const int B = 256;
    const int nodes_blk = (NUM_NODES + B - 1) / B;
    const int edges_blk = (N_EDGES + B - 1) / B;
    const int vec_blk   = (NUM_NODES * EMB_DIM / 4 + B - 1) / B;
    const long long gth = (long long)NUM_NODES * 8;
    const int gather_blk = (int)((gth + B - 1) / B);

    // ---- build CSR + fp16 source ----
    k_zero<<<nodes_blk, B>>>();
    k_init16<<<vec_blk, B>>>((const float4*)w);
    k_count_deg<<<edges_blk, B>>>(col);
    k_scan_block<<<SCAN_GRID, SCAN_B>>>();
    k_scan_part<<<1, 32>>>();
    k_scan_add<<<SCAN_GRID, SCAN_B>>>();
    k_fill<<<edges_blk, B>>>(row, col);

    // ---- 3 propagation layers, atomic-free pipelined gathers ----
    k_gather<<<gather_blk, B>>>(0, (const float4*)w, (float4*)out);
    k_gather<<<gather_blk, B>>>(1, (const float4*)w, (float4*)out);
    k_gather<<<gather_blk, B>>>(2, (const float4*)w, (float4*)out);
}

// round 7
// speedup vs baseline: 2.9151x; 1.0365x over previous
#include <cuda_runtime.h>
#include <cuda_fp16.h>

#define NUM_NODES 150000
#define EMB_DIM   64
#define N_EDGES   4000000
#define SCAN_B    1024
#define SCAN_GRID ((NUM_NODES + SCAN_B - 1) / SCAN_B)   // 147

__device__ __forceinline__ unsigned int h2_to_u32(__half2 h) {
    return *reinterpret_cast<unsigned int*>(&h);
}
__device__ __forceinline__ __half2 u32_to_h2(unsigned int u) {
    return *reinterpret_cast<__half2*>(&u);
}

// ---- scratch (static device globals; addresses taken ONLY in device code) ----
__device__ __half g_w16 [NUM_NODES * EMB_DIM];   // fp16 copy of w (layer-0 src)
__device__ __half g_l16A[NUM_NODES * EMB_DIM];   // fp16 layer-1 output
__device__ __half g_l16B[NUM_NODES * EMB_DIM];   // fp16 layer-2 output
__device__ int2   g_csr[N_EDGES];                // {src_row, norm_bits} grouped by col
__device__ int    g_offs[NUM_NODES + 1];
__device__ int    g_cur[NUM_NODES];
__device__ int    g_deg[NUM_NODES];
__device__ float  g_dis[NUM_NODES];
__device__ int    g_part[SCAN_GRID];

// ---- fused: zero counters + convert w -> fp16 ----
__global__ void k_init(const float4* __restrict__ w) {
    int i = blockIdx.x * blockDim.x + threadIdx.x;
    if (i < NUM_NODES * EMB_DIM / 4) {
        float4 v = w[i];
        uint2 h;
        h.x = h2_to_u32(__floats2half2_rn(v.x, v.y));
        h.y = h2_to_u32(__floats2half2_rn(v.z, v.w));
        ((uint2*)g_w16)[i] = h;
    }
    if (i < NUM_NODES) { g_deg[i] = 0; g_cur[i] = 0; }
}

__global__ void k_count_deg(const int* __restrict__ col) {
    int i = blockIdx.x * blockDim.x + threadIdx.x;
    if (i < N_EDGES) atomicAdd(&g_deg[col[i]], 1);
}

// ---- exclusive scan of g_deg into g_offs, fused with deg^-1/2 ----
__global__ void k_scan_block() {
    __shared__ int s[SCAN_B];
    int gid = blockIdx.x * SCAN_B + threadIdx.x;
    int v = (gid < NUM_NODES) ? g_deg[gid] : 0;
    s[threadIdx.x] = v;
    __syncthreads();
    for (int off = 1; off < SCAN_B; off <<= 1) {
        int t = (threadIdx.x >= off) ? s[threadIdx.x - off] : 0;
        __syncthreads();
        s[threadIdx.x] += t;
        __syncthreads();
    }
    if (gid < NUM_NODES) {
        g_offs[gid] = s[threadIdx.x] - v;
        g_dis[gid] = (v > 0) ? rsqrtf((float)v) : 0.0f;
    }
    if (threadIdx.x == SCAN_B - 1) g_part[blockIdx.x] = s[SCAN_B - 1];
}

// ---- parallel exclusive scan of the 147 block partials (was serial!) ----
__global__ void k_scan_part() {
    __shared__ int s[256];
    int v = (threadIdx.x < SCAN_GRID) ? g_part[threadIdx.x] : 0;
    s[threadIdx.x] = v;
    __syncthreads();
    for (int off = 1; off < 256; off <<= 1) {
        int t = (threadIdx.x >= off) ? s[threadIdx.x - off] : 0;
        __syncthreads();
        s[threadIdx.x] += t;
        __syncthreads();
    }
    if (threadIdx.x < SCAN_GRID) g_part[threadIdx.x] = s[threadIdx.x] - v;
}

__global__ void k_scan_add() {
    int gid = blockIdx.x * SCAN_B + threadIdx.x;
    if (gid < NUM_NODES) g_offs[gid] += g_part[blockIdx.x];
    if (gid == 0) g_offs[NUM_NODES] = N_EDGES;
}

// ---- fill CSR grouped by destination col, norm precomputed ----
__global__ void k_fill(const int* __restrict__ row, const int* __restrict__ col) {
    int e = blockIdx.x * blockDim.x + threadIdx.x;
    if (e >= N_EDGES) return;
    int r = row[e];
    int c = col[e];
    int pos = g_offs[c] + atomicAdd(&g_cur[c], 1);
    g_csr[pos] = make_int2(r, __float_as_int(g_dis[r] * g_dis[c]));
}

// ---- accumulate one fp16 row chunk (8 halves) into 8 fp32 accumulators ----
__device__ __forceinline__ void acc8(float* a, uint4 hv, float nrm) {
    float2 f0 = __half22float2(u32_to_h2(hv.x));
    float2 f1 = __half22float2(u32_to_h2(hv.y));
    float2 f2 = __half22float2(u32_to_h2(hv.z));
    float2 f3 = __half22float2(u32_to_h2(hv.w));
    a[0] += nrm * f0.x; a[1] += nrm * f0.y;
    a[2] += nrm * f1.x; a[3] += nrm * f1.y;
    a[4] += nrm * f2.x; a[5] += nrm * f2.y;
    a[6] += nrm * f3.x; a[7] += nrm * f3.y;
}

// ---- per-layer gather: 8 lanes per node, 16B per lane, 8-edge pipeline ----
//   layer 0: src=g_w16,  dst16=g_l16A, out  = w + acc
//   layer 1: src=g_l16A, dst16=g_l16B, out += acc
//   layer 2: src=g_l16B,              out  = 0.25*(out + acc)
__global__ void k_gather(int layer,
                         const float4* __restrict__ w,
                         float4* __restrict__ out) {
    int t = blockIdx.x * blockDim.x + threadIdx.x;
    int node = t >> 3, lane = t & 7;
    if (node >= NUM_NODES) return;

    const uint4* src;
    if (layer == 0)      src = (const uint4*)g_w16;
    else if (layer == 1) src = (const uint4*)g_l16A;
    else                 src = (const uint4*)g_l16B;

    int s = g_offs[node], e = g_offs[node + 1];
    float acc[8] = {0.f, 0.f, 0.f, 0.f, 0.f, 0.f, 0.f, 0.f};

    int j = s;
    for (; j + 8 <= e; j += 8) {
        int2 e0 = __ldg(&g_csr[j + 0]);
        int2 e1 = __ldg(&g_csr[j + 1]);
        int2 e2 = __ldg(&g_csr[j + 2]);
        int2 e3 = __ldg(&g_csr[j + 3]);
        int2 e4 = __ldg(&g_csr[j + 4]);
        int2 e5 = __ldg(&g_csr[j + 5]);
        int2 e6 = __ldg(&g_csr[j + 6]);
        int2 e7 = __ldg(&g_csr[j + 7]);
        uint4 v0 = __ldg(&src[e0.x * 8 + lane]);
        uint4 v1 = __ldg(&src[e1.x * 8 + lane]);
        uint4 v2 = __ldg(&src[e2.x * 8 + lane]);
        uint4 v3 = __ldg(&src[e3.x * 8 + lane]);
        uint4 v4 = __ldg(&src[e4.x * 8 + lane]);
        uint4 v5 = __ldg(&src[e5.x * 8 + lane]);
        uint4 v6 = __ldg(&src[e6.x * 8 + lane]);
        uint4 v7 = __ldg(&src[e7.x * 8 + lane]);
        acc8(acc, v0, __int_as_float(e0.y));
        acc8(acc, v1, __int_as_float(e1.y));
        acc8(acc, v2, __int_as_float(e2.y));
        acc8(acc, v3, __int_as_float(e3.y));
        acc8(acc, v4, __int_as_float(e4.y));
        acc8(acc, v5, __int_as_float(e5.y));
        acc8(acc, v6, __int_as_float(e6.y));
        acc8(acc, v7, __int_as_float(e7.y));
    }
    for (; j + 2 <= e; j += 2) {
        int2 ea = __ldg(&g_csr[j]);
        int2 eb = __ldg(&g_csr[j + 1]);
        uint4 va = __ldg(&src[ea.x * 8 + lane]);
        uint4 vb = __ldg(&src[eb.x * 8 + lane]);
        acc8(acc, va, __int_as_float(ea.y));
        acc8(acc, vb, __int_as_float(eb.y));
    }
    if (j < e) {
        int2 pr = __ldg(&g_csr[j]);
        uint4 v = __ldg(&src[pr.x * 8 + lane]);
        acc8(acc, v, __int_as_float(pr.y));
    }

    // fp16 store for next layer (layers 0,1)
    int i16 = node * 8 + lane;
    if (layer != 2) {
        uint4 h;
        h.x = h2_to_u32(__floats2half2_rn(acc[0], acc[1]));
        h.y = h2_to_u32(__floats2half2_rn(acc[2], acc[3]));
        h.z = h2_to_u32(__floats2half2_rn(acc[4], acc[5]));
        h.w = h2_to_u32(__floats2half2_rn(acc[6], acc[7]));
        if (layer == 0) ((uint4*)g_l16A)[i16] = h;
        else            ((uint4*)g_l16B)[i16] = h;
    }

    // fp32 running sum in out
    int i = node * 16 + lane * 2;
    if (layer == 0) {
        float4 a0 = w[i], a1 = w[i + 1];
        out[i]     = make_float4(a0.x + acc[0], a0.y + acc[1], a0.z + acc[2], a0.w + acc[3]);
        out[i + 1] = make_float4(a1.x + acc[4], a1.y + acc[5], a1.z + acc[6], a1.w + acc[7]);
    } else if (layer == 1) {
        float4 a0 = out[i], a1 = out[i + 1];
        out[i]     = make_float4(a0.x + acc[0], a0.y + acc[1], a0.z + acc[2], a0.w + acc[3]);
        out[i + 1] = make_float4(a1.x + acc[4], a1.y + acc[5], a1.z + acc[6], a1.w + acc[7]);
    } else {
        const float q = 0.25f;
        float4 a0 = out[i], a1 = out[i + 1];
        out[i]     = make_float4(q * (a0.x + acc[0]), q * (a0.y + acc[1]),
                                 q * (a0.z + acc[2]), q * (a0.w + acc[3]));
        out[i + 1] = make_float4(q * (a1.x + acc[4]), q * (a1.y + acc[5]),
                                 q * (a1.z + acc[6]), q * (a1.w + acc[7]));
    }
}

extern "C" void kernel_launch(void* const* d_in, const int* in_sizes, int n_in,
                              void* d_out, int out_size) {
    const int*   edge = (const int*)d_in[0];     // [2, N_EDGES] int32
    const int*   row  = edge;
    const int*   col  = edge + N_EDGES;
    const float* w    = (const float*)d_in[1];   // [NUM_NODES, EMB_DIM] f32
    float*       out  = (float*)d_out;

    const int B = 256;
    const int edges_blk = (N_EDGES + B - 1) / B;
    const int vec_blk   = (NUM_NODES * EMB_DIM / 4 + B - 1) / B;
    const long long gth = (long long)NUM_NODES * 8;
    const int gather_blk = (int)((gth + B - 1) / B);

    // ---- build CSR + fp16 source ----
    k_init<<<vec_blk, B>>>((const float4*)w);
    k_count_deg<<<edges_blk, B>>>(col);
    k_scan_block<<<SCAN_GRID, SCAN_B>>>();
    k_scan_part<<<1, 256>>>();
    k_scan_add<<<SCAN_GRID, SCAN_B>>>();
    k_fill<<<edges_blk, B>>>(row, col);

    // ---- 3 propagation layers, atomic-free pipelined gathers ----
    k_gather<<<gather_blk, B>>>(0, (const float4*)w, (float4*)out);
    k_gather<<<gather_blk, B>>>(1, (const float4*)w, (float4*)out);
    k_gather<<<gather_blk, B>>>(2, (const float4*)w, (float4*)out);
}